// round 11
// baseline (speedup 1.0000x reference)
#include <cuda_runtime.h>

#define TPB 128
#define APT 4                 // anchors per thread (k_phase1)
#define CHUNK (TPB * APT)     // anchors per block = 512
#define NW   (TPB / 32)       // warps per block
#define MAXN 128              // max gt boxes per image supported
#define MAXB 16               // max batch

// Scratch (device globals; no allocation allowed)
__device__ unsigned long long g_partial[1 << 19];  // per-(b,n) per-chunk best keys
__device__ unsigned long long g_abest[1 << 20];    // per-(b,a) packed (iou, box idx)
__device__ int                g_winner[1 << 20];   // per-(b,a) segment_max winner
__device__ float              g_miou[MAXB * MAXN]; // per-(b,n) max iou over anchors
__device__ unsigned           g_cnt[MAXB];         // per-batch finished-chunk count

// K1: for each (batch, 512-anchor chunk): compute all IoUs vs N boxes once.
//  - per-anchor best (axis=1 argmax, strict > = first occurrence) -> g_abest
//  - per-box block-best (axis=0 argmax candidate, tie -> lowest anchor) -> g_partial
//  - init g_winner = -1
//  - LAST block of each batch (threadfence-counter) folds in the old k_phase2:
//    reduces chunk partials per (b,n) -> g_miou + segment_max winner scatter.
__global__ void __launch_bounds__(TPB)
k_phase1(const float4* __restrict__ anchors, const float4* __restrict__ bboxes,
         int A, int N, int numChunks)
{
    __shared__ float4 sbox[MAXN];
    __shared__ float  sarea[MAXN];
    __shared__ unsigned long long swb[MAXN * NW];
    __shared__ int s_last;

    const int b = blockIdx.y, chunk = blockIdx.x, tid = threadIdx.x;
    const int lane = tid & 31, wid = tid >> 5;

    for (int n = tid; n < N; n += TPB) {
        float4 bb = bboxes[b * N + n];
        sbox[n] = bb;
        sarea[n] = (bb.z - bb.x) * (bb.w - bb.y);
    }
    __syncthreads();

    // Load APT anchors (stride TPB so within-warp anchor order == lane order)
    float ax1[APT], ay1[APT], ax2[APT], ay2[APT], areaA[APT];
    unsigned aidx[APT];
    bool avalid[APT];
    #pragma unroll
    for (int k = 0; k < APT; k++) {
        int a = chunk * CHUNK + k * TPB + tid;
        aidx[k] = (unsigned)a;
        avalid[k] = (a < A);
        if (avalid[k]) {
            float4 c = anchors[a];
            ax1[k] = c.x - c.z * 0.5f;  ay1[k] = c.y - c.w * 0.5f;
            ax2[k] = c.x + c.z * 0.5f;  ay2[k] = c.y + c.w * 0.5f;
            areaA[k] = (ax2[k] - ax1[k]) * (ay2[k] - ay1[k]);  // reference order
            g_winner[(size_t)b * A + a] = -1;
        } else {
            // dummy: zero extent -> IoU exactly 0 vs any valid box; index larger
            // than every real anchor so it never wins a tie-break.
            ax1[k] = 0.f; ay1[k] = 0.f; ax2[k] = 0.f; ay2[k] = 0.f;
            areaA[k] = 0.f;
        }
    }

    float bestI[APT];
    int   bestN[APT];
    #pragma unroll
    for (int k = 0; k < APT; k++) { bestI[k] = 0.0f; bestN[k] = 0; }

    for (int n = 0; n < N; n++) {
        float4 bb = sbox[n];
        float sa = sarea[n];

        float iou[APT];
        #pragma unroll
        for (int k = 0; k < APT; k++) {
            float ltx = fmaxf(ax1[k], bb.x), lty = fmaxf(ay1[k], bb.y);
            float rbx = fminf(ax2[k], bb.z), rby = fminf(ay2[k], bb.w);
            float w = fmaxf(rbx - ltx, 0.f), h = fmaxf(rby - lty, 0.f);
            float inter = w * h;
            iou[k] = __fdividef(inter, areaA[k] + sa - inter);
        }

        // per-anchor running argmax (strict > = first occurrence)
        #pragma unroll
        for (int k = 0; k < APT; k++)
            if (iou[k] > bestI[k]) { bestI[k] = iou[k]; bestN[k] = n; }

        // merge the APT anchors (strict > keeps earlier = lower anchor index)
        float    mi = iou[0];
        unsigned wa = aidx[0];
        #pragma unroll
        for (int k = 1; k < APT; k++)
            if (iou[k] > mi) { mi = iou[k]; wa = aidx[k]; }

        // warp argmax over anchors for this box: max IoU (uint-monotone, IoU>=0),
        // tie -> min anchor index.
        unsigned u = __float_as_uint(mi);
        unsigned m = __reduce_max_sync(0xffffffffu, u);
        unsigned cand = (u == m) ? wa : 0xFFFFFFFFu;
        unsigned amin = __reduce_min_sync(0xffffffffu, cand);
        if (lane == 0)
            swb[n * NW + wid] =
                ((unsigned long long)m << 32) | (0xFFFFFFFFu - amin);
    }

    #pragma unroll
    for (int k = 0; k < APT; k++)
        if (avalid[k])
            g_abest[(size_t)b * A + aidx[k]] =
                ((unsigned long long)__float_as_uint(bestI[k]) << 32) |
                (unsigned)bestN[k];

    __syncthreads();
    for (int n = tid; n < N; n += TPB) {
        unsigned long long best = swb[n * NW];
        #pragma unroll
        for (int w8 = 1; w8 < NW; w8++)
            if (swb[n * NW + w8] > best) best = swb[n * NW + w8];
        g_partial[((size_t)(b * N + n)) * numChunks + chunk] = best;
    }

    // ---- last-block-per-batch: fold in old k_phase2 ----
    __threadfence();
    __syncthreads();
    if (tid == 0) {
        unsigned ticket = atomicAdd(&g_cnt[b], 1u);
        s_last = (ticket == (unsigned)(numChunks - 1));
        if (s_last) g_cnt[b] = 0;   // reset for next graph replay
    }
    __syncthreads();
    if (!s_last) return;

    // This block runs after ALL chunks of batch b have published g_partial,
    // g_abest and g_winner init (threadfence + counter pattern).
    for (int n = tid; n < N; n += TPB) {
        const unsigned long long* p = g_partial + (size_t)(b * N + n) * numChunks;
        unsigned long long key = 0;
        #pragma unroll 8
        for (int c = 0; c < numChunks; c++) {
            unsigned long long v = p[c];
            if (v > key) key = v;
        }
        float miou = __uint_as_float((unsigned)(key >> 32));
        int   idx  = (int)(0xFFFFFFFFu - (unsigned)key);
        g_miou[b * N + n] = miou;
        atomicMax(&g_winner[(size_t)b * A + idx], n);
    }
}

// K3: epilogue, 4 anchors per thread (batched loads -> MLP): winner override,
//     scores, conf scatter, delta encode.
#define IPT 4
__global__ void __launch_bounds__(256)
k_phase3(const float4* __restrict__ anchors, const float4* __restrict__ bboxes,
         const int* __restrict__ labels,
         const float* __restrict__ enc_mean, const float* __restrict__ enc_std,
         const float* __restrict__ thr_ptr,
         float* __restrict__ out_conf, float4* __restrict__ out_delta,
         int A, int N, int C)
{
    __shared__ float4 sbox[MAXN];
    __shared__ int    slab[MAXN];
    __shared__ float  smiou[MAXN];

    const int b = blockIdx.y, tid = threadIdx.x;
    for (int n = tid; n < N; n += 256) {
        sbox[n]  = bboxes[b * N + n];
        slab[n]  = labels[b * N + n];
        smiou[n] = g_miou[b * N + n];
    }
    __syncthreads();

    const float thr = __ldg(thr_ptr);
    const float em0 = __ldg(&enc_mean[0]), em1 = __ldg(&enc_mean[1]);
    const float em2 = __ldg(&enc_mean[2]), em3 = __ldg(&enc_mean[3]);
    const float rs0 = 1.0f / __ldg(&enc_std[0]), rs1 = 1.0f / __ldg(&enc_std[1]);
    const float rs2 = 1.0f / __ldg(&enc_std[2]), rs3 = 1.0f / __ldg(&enc_std[3]);

    // batch all independent global loads first (MLP = 3*IPT)
    int a[IPT]; bool v[IPT];
    unsigned long long ab[IPT];
    int w[IPT];
    float4 anc[IPT];
    #pragma unroll
    for (int h = 0; h < IPT; h++) {
        a[h] = blockIdx.x * (256 * IPT) + h * 256 + tid;
        v[h] = (a[h] < A);
        if (v[h]) {
            size_t base = (size_t)b * A + a[h];
            ab[h]  = g_abest[base];
            w[h]   = g_winner[base];
            anc[h] = __ldg(&anchors[a[h]]);
        }
    }

    #pragma unroll
    for (int h = 0; h < IPT; h++) {
        if (!v[h]) continue;
        const size_t base = (size_t)b * A + a[h];

        float miou = __uint_as_float((unsigned)(ab[h] >> 32));
        int   idx  = (int)(unsigned)ab[h];
        if (w[h] >= 0) { idx = w[h]; miou = smiou[w[h]]; }

        float den = fmaxf(smiou[idx], thr);
        if (miou < thr * 0.5f) miou = 0.f;
        float score = miou / den;

        int lab = slab[idx];
        if (lab <= 0) { score = 0.f; lab = 0; }

        for (int c = 0; c < C; c++)
            out_conf[base * C + c] = (lab == c + 1) ? score : 0.f;

        float4 m = sbox[idx];
        float mcx = (m.x + m.z) * 0.5f, mcy = (m.y + m.w) * 0.5f;
        float mw  = m.z - m.x,          mh  = m.w - m.y;
        float d0 = (mcx - anc[h].x) / anc[h].z;
        float d1 = (mcy - anc[h].y) / anc[h].w;
        float d2 = __logf(mw / anc[h].z);
        float d3 = __logf(mh / anc[h].w);
        float4 dv;
        dv.x = (d0 - em0) * rs0;
        dv.y = (d1 - em1) * rs1;
        dv.z = (d2 - em2) * rs2;
        dv.w = (d3 - em3) * rs3;
        out_delta[base] = dv;
    }
}

extern "C" void kernel_launch(void* const* d_in, const int* in_sizes, int n_in,
                              void* d_out, int out_size)
{
    const float* anchors = (const float*)d_in[0];
    const int*   labels  = (const int*)d_in[1];
    const float* bboxes  = (const float*)d_in[2];
    const float* emean   = (const float*)d_in[3];
    const float* estd    = (const float*)d_in[4];
    const float* thr     = (const float*)d_in[5];

    const int A  = in_sizes[0] / 4;          // anchors [A,4]
    const int BN = in_sizes[1];              // labels [B,N]
    int B = out_size / (5 * A);
    if (B <= 0) B = 1;
    const int N = BN / B;
    const int C = (int)((long)out_size / ((long)B * A)) - 4;

    const float4* anc4 = (const float4*)anchors;
    const float4* box4 = (const float4*)bboxes;

    const int numChunks = (A + CHUNK - 1) / CHUNK;
    dim3 grid1(numChunks, B);
    k_phase1<<<grid1, TPB>>>(anc4, box4, A, N, numChunks);

    float*  out_conf  = (float*)d_out;
    float4* out_delta = (float4*)((float*)d_out + (size_t)B * A * C);
    dim3 g3((A + 256 * IPT - 1) / (256 * IPT), B);
    k_phase3<<<g3, 256>>>(anc4, box4, labels, emean, estd, thr,
                          out_conf, out_delta, A, N, C);
}

// round 12
// speedup vs baseline: 1.2372x; 1.2372x over previous
#include <cuda_runtime.h>

#define TPB 128
#define APT 4                 // anchors per thread (k_phase1)
#define CHUNK (TPB * APT)     // anchors per block = 512
#define MAXN 128              // max gt boxes per image supported
#define MAXB 16               // max batch

// Scratch (device globals; no allocation allowed)
__device__ unsigned long long g_partial[1 << 19];  // per-(b,n) per-chunk best keys
// g_pack[b*A+a] = { u64 abest key (iou<<32 | boxidx), int winner, int pad }
__device__ longlong2          g_pack[1 << 20];
__device__ float              g_miou[MAXB * MAXN]; // per-(b,n) max iou over anchors

// K1: for each (batch, 512-anchor chunk): compute all IoUs vs N boxes once.
//  - per-anchor best (axis=1 argmax, strict > = first occurrence) -> g_pack.ab
//    (single STG.128 also initializes winner = -1)
//  - per-box best over block (axis=0 argmax candidate, tie -> lowest anchor):
//    1 REDUX.MAX + predicated smem atomicMax on packed (iou, ~anchor) keys.
__global__ void __launch_bounds__(TPB)
k_phase1(const float4* __restrict__ anchors, const float4* __restrict__ bboxes,
         int A, int N, int numChunks)
{
    __shared__ float4 sbox[MAXN];
    __shared__ float  sarea[MAXN];
    __shared__ unsigned long long pbs[MAXN];

    const int b = blockIdx.y, chunk = blockIdx.x, tid = threadIdx.x;

    for (int n = tid; n < N; n += TPB) {
        float4 bb = bboxes[b * N + n];
        sbox[n] = bb;
        sarea[n] = (bb.z - bb.x) * (bb.w - bb.y);
        // init: iou=0, anchor=0 (complemented) — matches reference argmax of an
        // all-zero column (= anchor 0).
        pbs[n] = 0x00000000FFFFFFFFull;
    }
    __syncthreads();

    // Load APT anchors (stride TPB so within-warp anchor order == lane order)
    float ax1[APT], ay1[APT], ax2[APT], ay2[APT], areaA[APT];
    unsigned naidx[APT];   // complemented anchor index (loop-invariant)
    bool avalid[APT];
    #pragma unroll
    for (int k = 0; k < APT; k++) {
        int a = chunk * CHUNK + k * TPB + tid;
        naidx[k] = 0xFFFFFFFFu - (unsigned)a;
        avalid[k] = (a < A);
        if (avalid[k]) {
            float4 c = anchors[a];
            ax1[k] = c.x - c.z * 0.5f;  ay1[k] = c.y - c.w * 0.5f;
            ax2[k] = c.x + c.z * 0.5f;  ay2[k] = c.y + c.w * 0.5f;
            areaA[k] = (ax2[k] - ax1[k]) * (ay2[k] - ay1[k]);  // reference order
        } else {
            // dummy: zero extent -> IoU exactly 0 vs any valid box; index larger
            // than every real anchor so it never wins a tie-break.
            ax1[k] = 0.f; ay1[k] = 0.f; ax2[k] = 0.f; ay2[k] = 0.f;
            areaA[k] = 0.f;
        }
    }

    float bestI[APT];
    int   bestN[APT];
    #pragma unroll
    for (int k = 0; k < APT; k++) { bestI[k] = 0.0f; bestN[k] = 0; }

    for (int n = 0; n < N; n++) {
        float4 bb = sbox[n];
        float sa = sarea[n];

        float iou[APT];
        #pragma unroll
        for (int k = 0; k < APT; k++) {
            float ltx = fmaxf(ax1[k], bb.x), lty = fmaxf(ay1[k], bb.y);
            float rbx = fminf(ax2[k], bb.z), rby = fminf(ay2[k], bb.w);
            float w = fmaxf(rbx - ltx, 0.f), h = fmaxf(rby - lty, 0.f);
            float inter = w * h;
            iou[k] = __fdividef(inter, areaA[k] + sa - inter);
        }

        // per-anchor running argmax (strict > = first occurrence)
        #pragma unroll
        for (int k = 0; k < APT; k++)
            if (iou[k] > bestI[k]) { bestI[k] = iou[k]; bestN[k] = n; }

        // merge the APT anchors (strict > keeps earlier = lower anchor index)
        float    mi = iou[0];
        unsigned nsel = naidx[0];
        #pragma unroll
        for (int k = 1; k < APT; k++)
            if (iou[k] > mi) { mi = iou[k]; nsel = naidx[k]; }

        // warp max IoU for this box (uint-monotone, IoU>=0). Lanes holding the
        // max push their own packed key; the smem atomic resolves cross-lane,
        // cross-warp AND tie (max ~anchor = min anchor) in one op. m==0 is the
        // init value: skip (also avoids 32-lane same-address serialization on
        // non-overlapping boxes).
        unsigned u = __float_as_uint(mi);
        unsigned m = __reduce_max_sync(0xffffffffu, u);
        if (u == m && m != 0u)
            atomicMax(&pbs[n], ((unsigned long long)m << 32) | nsel);
    }

    // per-anchor: single 16B store = abest key + winner init (-1) + pad (0)
    #pragma unroll
    for (int k = 0; k < APT; k++)
        if (avalid[k]) {
            unsigned long long key =
                ((unsigned long long)__float_as_uint(bestI[k]) << 32) |
                (unsigned)bestN[k];
            longlong2 v;
            v.x = (long long)key;
            v.y = (long long)0xFFFFFFFFull;   // winner=-1 (low 32), pad=0
            g_pack[(size_t)b * A + (0xFFFFFFFFu - naidx[k])] = v;
        }

    __syncthreads();
    for (int n = tid; n < N; n += TPB)
        g_partial[((size_t)(b * N + n)) * numChunks + chunk] = pbs[n];
}

// K2: reduce chunk partials per (b,n) -> max_iou_of_bbox + anchor argmax,
//     then segment_max scatter: winner[anchor] = max n claiming it.
__global__ void __launch_bounds__(64)
k_phase2(int A, int N, int numChunks)
{
    const int bn = blockIdx.x, tid = threadIdx.x;
    const unsigned long long* p = g_partial + (size_t)bn * numChunks;

    unsigned long long key = 0;
    for (int c = tid; c < numChunks; c += 64) {
        unsigned long long v = p[c];
        if (v > key) key = v;
    }
    __shared__ unsigned long long sred[2];
    #pragma unroll
    for (int off = 16; off; off >>= 1) {
        unsigned long long o = __shfl_down_sync(0xffffffffu, key, off);
        if (o > key) key = o;
    }
    if ((tid & 31) == 0) sred[tid >> 5] = key;
    __syncthreads();
    if (tid == 0) {
        if (sred[1] > key) key = sred[1];
        float miou = __uint_as_float((unsigned)(key >> 32));
        int   idx  = (int)(0xFFFFFFFFu - (unsigned)key);
        g_miou[bn] = miou;
        int b = bn / N, n = bn - b * N;
        atomicMax((int*)&g_pack[(size_t)b * A + idx] + 2, n);  // winner field
    }
}

// K3: epilogue, 2 anchors per thread (batched 16B loads): winner override,
//     scores, conf scatter, delta encode.
#define IPT 2
__global__ void __launch_bounds__(256)
k_phase3(const float4* __restrict__ anchors, const float4* __restrict__ bboxes,
         const int* __restrict__ labels,
         const float* __restrict__ enc_mean, const float* __restrict__ enc_std,
         const float* __restrict__ thr_ptr,
         float* __restrict__ out_conf, float4* __restrict__ out_delta,
         int A, int N, int C)
{
    __shared__ float4 sbox[MAXN];
    __shared__ int    slab[MAXN];
    __shared__ float  smiou[MAXN];

    const int b = blockIdx.y, tid = threadIdx.x;
    for (int n = tid; n < N; n += 256) {
        sbox[n]  = bboxes[b * N + n];
        slab[n]  = labels[b * N + n];
        smiou[n] = g_miou[b * N + n];
    }
    __syncthreads();

    const float thr = __ldg(thr_ptr);
    const float em0 = __ldg(&enc_mean[0]), em1 = __ldg(&enc_mean[1]);
    const float em2 = __ldg(&enc_mean[2]), em3 = __ldg(&enc_mean[3]);
    const float rs0 = 1.0f / __ldg(&enc_std[0]), rs1 = 1.0f / __ldg(&enc_std[1]);
    const float rs2 = 1.0f / __ldg(&enc_std[2]), rs3 = 1.0f / __ldg(&enc_std[3]);

    // batch independent global loads first (MLP = 2*IPT)
    int a[IPT]; bool v[IPT];
    longlong2 pk[IPT];
    float4 anc[IPT];
    #pragma unroll
    for (int h = 0; h < IPT; h++) {
        a[h] = blockIdx.x * (256 * IPT) + h * 256 + tid;
        v[h] = (a[h] < A);
        if (v[h]) {
            pk[h]  = g_pack[(size_t)b * A + a[h]];
            anc[h] = __ldg(&anchors[a[h]]);
        }
    }

    #pragma unroll
    for (int h = 0; h < IPT; h++) {
        if (!v[h]) continue;
        const size_t base = (size_t)b * A + a[h];

        unsigned long long ab = (unsigned long long)pk[h].x;
        int w = (int)pk[h].y;              // low 32 bits = winner

        float miou = __uint_as_float((unsigned)(ab >> 32));
        int   idx  = (int)(unsigned)ab;
        if (w >= 0) { idx = w; miou = smiou[w]; }

        float den = fmaxf(smiou[idx], thr);
        if (miou < thr * 0.5f) miou = 0.f;
        float score = miou / den;

        int lab = slab[idx];
        if (lab <= 0) { score = 0.f; lab = 0; }

        for (int c = 0; c < C; c++)
            out_conf[base * C + c] = (lab == c + 1) ? score : 0.f;

        float4 m = sbox[idx];
        float mcx = (m.x + m.z) * 0.5f, mcy = (m.y + m.w) * 0.5f;
        float mw  = m.z - m.x,          mh  = m.w - m.y;
        float d0 = (mcx - anc[h].x) / anc[h].z;
        float d1 = (mcy - anc[h].y) / anc[h].w;
        float d2 = __logf(mw / anc[h].z);
        float d3 = __logf(mh / anc[h].w);
        float4 dv;
        dv.x = (d0 - em0) * rs0;
        dv.y = (d1 - em1) * rs1;
        dv.z = (d2 - em2) * rs2;
        dv.w = (d3 - em3) * rs3;
        out_delta[base] = dv;
    }
}

extern "C" void kernel_launch(void* const* d_in, const int* in_sizes, int n_in,
                              void* d_out, int out_size)
{
    const float* anchors = (const float*)d_in[0];
    const int*   labels  = (const int*)d_in[1];
    const float* bboxes  = (const float*)d_in[2];
    const float* emean   = (const float*)d_in[3];
    const float* estd    = (const float*)d_in[4];
    const float* thr     = (const float*)d_in[5];

    const int A  = in_sizes[0] / 4;          // anchors [A,4]
    const int BN = in_sizes[1];              // labels [B,N]
    int B = out_size / (5 * A);
    if (B <= 0) B = 1;
    const int N = BN / B;
    const int C = (int)((long)out_size / ((long)B * A)) - 4;

    const float4* anc4 = (const float4*)anchors;
    const float4* box4 = (const float4*)bboxes;

    const int numChunks = (A + CHUNK - 1) / CHUNK;
    dim3 grid1(numChunks, B);
    k_phase1<<<grid1, TPB>>>(anc4, box4, A, N, numChunks);

    k_phase2<<<B * N, 64>>>(A, N, numChunks);

    float*  out_conf  = (float*)d_out;
    float4* out_delta = (float4*)((float*)d_out + (size_t)B * A * C);
    dim3 g3((A + 256 * IPT - 1) / (256 * IPT), B);
    k_phase3<<<g3, 256>>>(anc4, box4, labels, emean, estd, thr,
                          out_conf, out_delta, A, N, C);
}

// round 13
// speedup vs baseline: 1.4173x; 1.1456x over previous
#include <cuda_runtime.h>

#define TPB 128
#define APT 4                 // anchors per thread (k_phase1)
#define CHUNK (TPB * APT)     // anchors per block = 512
#define NW   (TPB / 32)       // warps per block
#define MAXN 128              // max gt boxes per image supported
#define MAXB 16               // max batch
#define K3T 256               // k_phase3 threads
#define K3A 512               // anchors per k_phase3 block

// Scratch (device globals; no allocation allowed)
__device__ unsigned long long g_partial[1 << 19];  // per-(b,n) per-chunk best keys
__device__ unsigned long long g_abest[1 << 20];    // per-(b,a) packed (iou, box idx)
__device__ float2             g_nbest[MAXB * MAXN];// per-(b,n): (miou, argmax anchor)

// K1: for each (batch, 512-anchor chunk): compute all IoUs vs N boxes once.
//  - per-anchor best (axis=1 argmax, strict > = first occurrence) -> g_abest
//  - per-box block-best (axis=0 argmax candidate, tie -> lowest anchor) -> g_partial
__global__ void __launch_bounds__(TPB)
k_phase1(const float4* __restrict__ anchors, const float4* __restrict__ bboxes,
         int A, int N, int numChunks)
{
    __shared__ float4 sbox[MAXN];
    __shared__ float  sarea[MAXN];
    __shared__ unsigned long long swb[MAXN * NW];

    const int b = blockIdx.y, chunk = blockIdx.x, tid = threadIdx.x;
    const int lane = tid & 31, wid = tid >> 5;

    for (int n = tid; n < N; n += TPB) {
        float4 bb = bboxes[b * N + n];
        sbox[n] = bb;
        sarea[n] = (bb.z - bb.x) * (bb.w - bb.y);
    }
    __syncthreads();

    // Load APT anchors (stride TPB so within-warp anchor order == lane order)
    float ax1[APT], ay1[APT], ax2[APT], ay2[APT], areaA[APT];
    unsigned aidx[APT];
    bool avalid[APT];
    #pragma unroll
    for (int k = 0; k < APT; k++) {
        int a = chunk * CHUNK + k * TPB + tid;
        aidx[k] = (unsigned)a;
        avalid[k] = (a < A);
        if (avalid[k]) {
            float4 c = anchors[a];
            ax1[k] = c.x - c.z * 0.5f;  ay1[k] = c.y - c.w * 0.5f;
            ax2[k] = c.x + c.z * 0.5f;  ay2[k] = c.y + c.w * 0.5f;
            areaA[k] = (ax2[k] - ax1[k]) * (ay2[k] - ay1[k]);  // reference order
        } else {
            // dummy: zero extent -> IoU exactly 0 vs any valid box; index larger
            // than every real anchor so it never wins a tie-break.
            ax1[k] = 0.f; ay1[k] = 0.f; ax2[k] = 0.f; ay2[k] = 0.f;
            areaA[k] = 0.f;
        }
    }

    float bestI[APT];
    int   bestN[APT];
    #pragma unroll
    for (int k = 0; k < APT; k++) { bestI[k] = 0.0f; bestN[k] = 0; }

    #pragma unroll 2
    for (int n = 0; n < N; n++) {
        float4 bb = sbox[n];
        float sa = sarea[n];

        float iou[APT];
        #pragma unroll
        for (int k = 0; k < APT; k++) {
            float ltx = fmaxf(ax1[k], bb.x), lty = fmaxf(ay1[k], bb.y);
            float rbx = fminf(ax2[k], bb.z), rby = fminf(ay2[k], bb.w);
            float w = fmaxf(rbx - ltx, 0.f), h = fmaxf(rby - lty, 0.f);
            float inter = w * h;
            iou[k] = __fdividef(inter, areaA[k] + sa - inter);
        }

        // per-anchor running argmax (strict > = first occurrence)
        #pragma unroll
        for (int k = 0; k < APT; k++)
            if (iou[k] > bestI[k]) { bestI[k] = iou[k]; bestN[k] = n; }

        // merge the APT anchors (strict > keeps earlier = lower anchor index)
        float    mi = iou[0];
        unsigned wa = aidx[0];
        #pragma unroll
        for (int k = 1; k < APT; k++)
            if (iou[k] > mi) { mi = iou[k]; wa = aidx[k]; }

        // warp argmax over anchors for this box: max IoU (uint-monotone, IoU>=0),
        // tie -> min anchor index.
        unsigned u = __float_as_uint(mi);
        unsigned m = __reduce_max_sync(0xffffffffu, u);
        unsigned cand = (u == m) ? wa : 0xFFFFFFFFu;
        unsigned amin = __reduce_min_sync(0xffffffffu, cand);
        if (lane == 0)
            swb[n * NW + wid] =
                ((unsigned long long)m << 32) | (0xFFFFFFFFu - amin);
    }

    #pragma unroll
    for (int k = 0; k < APT; k++)
        if (avalid[k])
            g_abest[(size_t)b * A + aidx[k]] =
                ((unsigned long long)__float_as_uint(bestI[k]) << 32) |
                (unsigned)bestN[k];

    __syncthreads();
    for (int n = tid; n < N; n += TPB) {
        unsigned long long best = swb[n * NW];
        #pragma unroll
        for (int w8 = 1; w8 < NW; w8++)
            if (swb[n * NW + w8] > best) best = swb[n * NW + w8];
        g_partial[((size_t)(b * N + n)) * numChunks + chunk] = best;
    }
}

// K2: reduce chunk partials per (b,n) -> (max_iou_of_bbox, anchor argmax).
__global__ void __launch_bounds__(64)
k_phase2(int A, int N, int numChunks)
{
    const int bn = blockIdx.x, tid = threadIdx.x;
    const unsigned long long* p = g_partial + (size_t)bn * numChunks;

    unsigned long long key = 0;
    for (int c = tid; c < numChunks; c += 64) {
        unsigned long long v = p[c];
        if (v > key) key = v;
    }
    __shared__ unsigned long long sred[2];
    #pragma unroll
    for (int off = 16; off; off >>= 1) {
        unsigned long long o = __shfl_down_sync(0xffffffffu, key, off);
        if (o > key) key = o;
    }
    if ((tid & 31) == 0) sred[tid >> 5] = key;
    __syncthreads();
    if (tid == 0) {
        if (sred[1] > key) key = sred[1];
        float miou = __uint_as_float((unsigned)(key >> 32));
        int   idx  = (int)(0xFFFFFFFFu - (unsigned)key);
        g_nbest[bn] = make_float2(miou, __int_as_float(idx));
    }
}

// K3: epilogue per 512-anchor block. Winner (segment_max over targets) is
// rebuilt LOCALLY in smem from the 100 per-box argmax anchors (identical to a
// global segment_max scatter, but read back via LDS instead of dependent LDG).
__global__ void __launch_bounds__(K3T)
k_phase3(const float4* __restrict__ anchors, const float4* __restrict__ bboxes,
         const int* __restrict__ labels,
         const float* __restrict__ enc_mean, const float* __restrict__ enc_std,
         const float* __restrict__ thr_ptr,
         float* __restrict__ out_conf, float4* __restrict__ out_delta,
         int A, int N, int C)
{
    __shared__ float4 sbox[MAXN];
    __shared__ int    slab[MAXN];
    __shared__ float  smiou[MAXN];
    __shared__ int    saw[MAXN];
    __shared__ int    swin[K3A];

    const int b = blockIdx.y, tid = threadIdx.x;
    const int abase = blockIdx.x * K3A;

    for (int n = tid; n < N; n += K3T) {
        sbox[n]  = bboxes[b * N + n];
        slab[n]  = labels[b * N + n];
        float2 nb = g_nbest[b * N + n];
        smiou[n] = nb.x;
        saw[n]   = __float_as_int(nb.y);
    }
    #pragma unroll
    for (int h = 0; h < K3A / K3T; h++) swin[h * K3T + tid] = -1;
    __syncthreads();

    // segment_max scatter restricted to this block's anchor range
    for (int n = tid; n < N; n += K3T) {
        int aw = saw[n] - abase;
        if ((unsigned)aw < (unsigned)K3A) atomicMax(&swin[aw], n);
    }
    __syncthreads();

    const float thr = __ldg(thr_ptr);
    const float em0 = __ldg(&enc_mean[0]), em1 = __ldg(&enc_mean[1]);
    const float em2 = __ldg(&enc_mean[2]), em3 = __ldg(&enc_mean[3]);
    const float rs0 = 1.0f / __ldg(&enc_std[0]), rs1 = 1.0f / __ldg(&enc_std[1]);
    const float rs2 = 1.0f / __ldg(&enc_std[2]), rs3 = 1.0f / __ldg(&enc_std[3]);

    // batch independent global loads (MLP across the 2 anchors)
    const int IP = K3A / K3T;   // 2
    int a[IP]; bool v[IP];
    unsigned long long ab[IP];
    float4 anc[IP];
    #pragma unroll
    for (int h = 0; h < IP; h++) {
        a[h] = abase + h * K3T + tid;
        v[h] = (a[h] < A);
        if (v[h]) {
            ab[h]  = g_abest[(size_t)b * A + a[h]];
            anc[h] = __ldg(&anchors[a[h]]);
        }
    }

    #pragma unroll
    for (int h = 0; h < IP; h++) {
        if (!v[h]) continue;
        const size_t base = (size_t)b * A + a[h];

        float miou = __uint_as_float((unsigned)(ab[h] >> 32));
        int   idx  = (int)(unsigned)ab[h];
        int w = swin[h * K3T + tid];
        if (w >= 0) { idx = w; miou = smiou[w]; }

        float den = fmaxf(smiou[idx], thr);
        if (miou < thr * 0.5f) miou = 0.f;
        float score = miou / den;

        int lab = slab[idx];
        if (lab <= 0) { score = 0.f; lab = 0; }

        for (int c = 0; c < C; c++)
            out_conf[base * C + c] = (lab == c + 1) ? score : 0.f;

        float4 m = sbox[idx];
        float mcx = (m.x + m.z) * 0.5f, mcy = (m.y + m.w) * 0.5f;
        float mw  = m.z - m.x,          mh  = m.w - m.y;
        float d0 = (mcx - anc[h].x) / anc[h].z;
        float d1 = (mcy - anc[h].y) / anc[h].w;
        float d2 = __logf(mw / anc[h].z);
        float d3 = __logf(mh / anc[h].w);
        float4 dv;
        dv.x = (d0 - em0) * rs0;
        dv.y = (d1 - em1) * rs1;
        dv.z = (d2 - em2) * rs2;
        dv.w = (d3 - em3) * rs3;
        out_delta[base] = dv;
    }
}

extern "C" void kernel_launch(void* const* d_in, const int* in_sizes, int n_in,
                              void* d_out, int out_size)
{
    const float* anchors = (const float*)d_in[0];
    const int*   labels  = (const int*)d_in[1];
    const float* bboxes  = (const float*)d_in[2];
    const float* emean   = (const float*)d_in[3];
    const float* estd    = (const float*)d_in[4];
    const float* thr     = (const float*)d_in[5];

    const int A  = in_sizes[0] / 4;          // anchors [A,4]
    const int BN = in_sizes[1];              // labels [B,N]
    int B = out_size / (5 * A);
    if (B <= 0) B = 1;
    const int N = BN / B;
    const int C = (int)((long)out_size / ((long)B * A)) - 4;

    const float4* anc4 = (const float4*)anchors;
    const float4* box4 = (const float4*)bboxes;

    const int numChunks = (A + CHUNK - 1) / CHUNK;
    dim3 grid1(numChunks, B);
    k_phase1<<<grid1, TPB>>>(anc4, box4, A, N, numChunks);

    k_phase2<<<B * N, 64>>>(A, N, numChunks);

    float*  out_conf  = (float*)d_out;
    float4* out_delta = (float4*)((float*)d_out + (size_t)B * A * C);
    dim3 g3((A + K3A - 1) / K3A, B);
    k_phase3<<<g3, K3T>>>(anc4, box4, labels, emean, estd, thr,
                          out_conf, out_delta, A, N, C);
}